// round 10
// baseline (speedup 1.0000x reference)
#include <cuda_runtime.h>
#include <cuda_bf16.h>
#include <cstdint>

// Problem constants (shape-specialized)
#define NY 496
#define NX 432
#define NZp 1
#define CCH 64
#define BATCH 4
#define SPATIAL (NY * NX * NZp)          // 214272
#define TOTAL_CELLS (BATCH * SPATIAL)    // 857088
#define CELLS_PER_BLK 128                // 2 tiles of 64; SPATIAL % 128 == 0
#define NBLOCKS (TOTAL_CELLS / CELLS_PER_BLK)  // 6696

// Per-cell winner voxel index + 1 (0 = empty). Zero-initialized at module
// load; k_gather resets every nonzero entry, so the all-zero invariant holds
// across graph replays. 3.27 MB static scratch — no runtime allocation.
__device__ int g_winner[TOTAL_CELLS];

// K1: last-write-wins vote (atomicMax(i+1) == sequential .at[].set order).
__global__ void k_vote(const int4* __restrict__ coors, int n) {
    int i = blockIdx.x * blockDim.x + threadIdx.x;
    if (i < n) {
        int4 c = coors[i];  // [b, z, y, x]
        int g = c.x * SPATIAL + c.z * (NX * NZp) + c.w * NZp + c.y;
        atomicMax(&g_winner[g], i + 1);
    }
}

// K2: 2 tiles (128 cells x 64 ch) per block, double-buffered smem, ONE
// __syncthreads. All 8 feature LDG.128 issued before any STS (8-deep MLP).
// XOR-swizzled smem (proven conflict-free in R7). Streaming STG (.cs) for
// the write-once output.
__global__ __launch_bounds__(256) void k_gather(const float4* __restrict__ feat4,
                                                float* __restrict__ out) {
    __shared__ float tile[CELLS_PER_BLK * 64];   // 32 KB

    const int tid  = threadIdx.x;
    const int w    = tid >> 5;           // warp 0..7
    const int lane = tid & 31;
    const int v    = tid & 15;           // float4 index within 64-ch row
    const int half = (tid >> 4) & 1;

    const int gcell0 = blockIdx.x * CELLS_PER_BLK;  // no batch straddle
    const int b      = gcell0 / SPATIAL;
    const int s0     = gcell0 - b * SPATIAL;

    // --- winners for both tiles: lanes 0..15 load + reset, then shfl ---
    int wv = 0;
    if (lane < 16) {
        int t  = lane >> 3;              // tile 0/1
        int l  = lane & 7;
        int cl = 2 * w + (l & 1) + 16 * (l >> 1) + 64 * t;
        wv = g_winner[gcell0 + cl];
        if (wv) g_winner[gcell0 + cl] = 0;   // restore all-zero invariant
    }
    const unsigned FULL = 0xFFFFFFFFu;
    int a0 = __shfl_sync(FULL, wv, half + 0);
    int a1 = __shfl_sync(FULL, wv, half + 2);
    int a2 = __shfl_sync(FULL, wv, half + 4);
    int a3 = __shfl_sync(FULL, wv, half + 6);
    int b0 = __shfl_sync(FULL, wv, half + 8);
    int b1 = __shfl_sync(FULL, wv, half + 10);
    int b2 = __shfl_sync(FULL, wv, half + 12);
    int b3 = __shfl_sync(FULL, wv, half + 14);

    // --- Phase A: 8 independent LDG.128 (2 tiles), then swizzled STS.128 ---
    const int cellb = 2 * w + half;                 // base cell within a tile
    const int col   = (4 * v) ^ (4 * (cellb & 7));  // swizzle (16p keeps cell&7)
    float4 z  = make_float4(0.f, 0.f, 0.f, 0.f);
    float4 fa0 = a0 ? feat4[(size_t)(a0 - 1) * (CCH / 4) + v] : z;
    float4 fa1 = a1 ? feat4[(size_t)(a1 - 1) * (CCH / 4) + v] : z;
    float4 fa2 = a2 ? feat4[(size_t)(a2 - 1) * (CCH / 4) + v] : z;
    float4 fa3 = a3 ? feat4[(size_t)(a3 - 1) * (CCH / 4) + v] : z;
    float4 fb0 = b0 ? feat4[(size_t)(b0 - 1) * (CCH / 4) + v] : z;
    float4 fb1 = b1 ? feat4[(size_t)(b1 - 1) * (CCH / 4) + v] : z;
    float4 fb2 = b2 ? feat4[(size_t)(b2 - 1) * (CCH / 4) + v] : z;
    float4 fb3 = b3 ? feat4[(size_t)(b3 - 1) * (CCH / 4) + v] : z;

    *reinterpret_cast<float4*>(&tile[(cellb +   0) * 64 + col]) = fa0;
    *reinterpret_cast<float4*>(&tile[(cellb +  16) * 64 + col]) = fa1;
    *reinterpret_cast<float4*>(&tile[(cellb +  32) * 64 + col]) = fa2;
    *reinterpret_cast<float4*>(&tile[(cellb +  48) * 64 + col]) = fa3;
    *reinterpret_cast<float4*>(&tile[(cellb +  64) * 64 + col]) = fb0;
    *reinterpret_cast<float4*>(&tile[(cellb +  80) * 64 + col]) = fb1;
    *reinterpret_cast<float4*>(&tile[(cellb +  96) * 64 + col]) = fb2;
    *reinterpret_cast<float4*>(&tile[(cellb + 112) * 64 + col]) = fb3;
    __syncthreads();   // the only barrier

    // --- Phase B: swizzled LDS.128 + streaming coalesced STG.32 ---
    float* outb = out + (size_t)b * CCH * SPATIAL + s0;
    const int swz = 4 * (lane & 7);
#pragma unroll
    for (int q = 0; q < 4; ++q) {                    // cell quarters of 128
        const int cell = lane + 32 * q;
#pragma unroll
        for (int gg = 0; gg < 2; ++gg) {             // channel groups w, w+8
            const int G = w + 8 * gg;
            float4 d = *reinterpret_cast<const float4*>(
                &tile[cell * 64 + ((4 * G) ^ swz)]);
            float* ob = outb + (size_t)(4 * G) * SPATIAL + cell;
            __stcs(ob + 0 * SPATIAL, d.x);
            __stcs(ob + 1 * SPATIAL, d.y);
            __stcs(ob + 2 * SPATIAL, d.z);
            __stcs(ob + 3 * SPATIAL, d.w);
        }
    }
}

extern "C" void kernel_launch(void* const* d_in, const int* in_sizes, int n_in,
                              void* d_out, int out_size) {
    const float4* feat4 = (const float4*)d_in[0];
    const int4*   coors = (const int4*)d_in[1];
    float*        out   = (float*)d_out;

    const int n = in_sizes[0] / CCH;  // 320000

    k_vote<<<(n + 255) / 256, 256>>>(coors, n);
    k_gather<<<NBLOCKS, 256>>>(feat4, out);
}